// round 9
// baseline (speedup 1.0000x reference)
#include <cuda_runtime.h>
#include <stdint.h>
#include <math.h>

#define BATCH   2
#define SEQ     2048
#define DMODEL  1024
#define NHEAD   16
#define DK      64
#define MTOT    (BATCH*SEQ)
#define OUT_OFF ((size_t)MTOT*DMODEL)

// Scratch: projections, attention output, softmax partial row sums
__device__ float g_qp[MTOT*DMODEL];
__device__ float g_kp[MTOT*DMODEL];
__device__ float g_vp[MTOT*DMODEL];
__device__ float g_ao[MTOT*DMODEL];
__device__ float g_zp[32*16*2048];     // [bh][colTile][row] partial rowsums

// ---------------------------------------------------------------------------
__device__ __forceinline__ uint32_t f2tf32(float x) {
    uint32_t u;
    asm("cvt.rna.tf32.f32 %0, %1;" : "=r"(u) : "f"(x));
    return u;
}

__device__ __forceinline__ void mma_tf32(float* d, const uint32_t* a, const uint32_t* b) {
    asm volatile(
        "mma.sync.aligned.m16n8k8.row.col.f32.tf32.tf32.f32 "
        "{%0,%1,%2,%3}, {%4,%5,%6,%7}, {%8,%9}, {%0,%1,%2,%3};"
        : "+f"(d[0]), "+f"(d[1]), "+f"(d[2]), "+f"(d[3])
        : "r"(a[0]), "r"(a[1]), "r"(a[2]), "r"(a[3]), "r"(b[0]), "r"(b[1]));
}

__device__ __forceinline__ void cp16(uint32_t saddr, const void* gptr) {
    asm volatile("cp.async.cg.shared.global [%0], [%1], 16;" :: "r"(saddr), "l"(gptr));
}
__device__ __forceinline__ void cp_commit() { asm volatile("cp.async.commit_group;"); }
__device__ __forceinline__ void cp_wait1()  { asm volatile("cp.async.wait_group 1;"); }
__device__ __forceinline__ void cp_wait0()  { asm volatile("cp.async.wait_group 0;"); }

// Fast exp on the FMA pipe (magic rounding + deg-6 poly), rel err ~1e-7.
__device__ __forceinline__ float fast_exp(float x) {
    x = fmaxf(x, -80.f);
    float t = x * 1.4426950408889634f;
    float z = t + 12582912.f;
    int   i = __float_as_int(z) - 0x4B400000;
    float f = t - (z - 12582912.f);
    float y = f * 0.6931471805599453f;
    float p = 1.f + y*(1.f + y*(0.5f + y*(0.16666667f + y*(0.041666668f +
              y*(0.008333334f + y*0.0013888889f)))));
    return p * __int_as_float((i + 127) << 23);
}

// ---------------------------------------------------------------------------
// NT core, BK=32: C[128x128] = alpha * A @ B^T. 2-stage cp.async,
// stage = As[128][36] + Bs[128][36] = 9216 floats (36864 B).
// ---------------------------------------------------------------------------
__device__ __forceinline__ void gemm_nt_core(
    const float* __restrict__ A, const float* __restrict__ B, float* __restrict__ C,
    int K, int lda, int ldb, int ldc, float alpha,
    int mBase, int nBase, float* dsm)
{
    const int tid  = threadIdx.x;
    const int lane = tid & 31;
    const int warp = tid >> 5;
    const int wm   = warp >> 2;
    const int wn   = warp & 3;
    const int q    = lane & 3;
    const int lr   = lane >> 2;
    const int lrow = tid >> 1;           // 0..127
    const int lcol = (tid & 1) * 16;     // 0 or 16 (floats)

    const uint32_t sbase = (uint32_t)__cvta_generic_to_shared(dsm);
    const float* Ag = A + (size_t)mBase * lda;
    const float* Bg = B + (size_t)nBase * ldb;

    float acc[4][4][4];
    #pragma unroll
    for (int i = 0; i < 4; i++)
        #pragma unroll
        for (int j = 0; j < 4; j++)
            #pragma unroll
            for (int t = 0; t < 4; t++) acc[i][j][t] = 0.f;

    const int nc = K >> 5;

    #define NT_ISSUE(st, k0) do {                                              \
        uint32_t ab = sbase + (st) * 36864u + (uint32_t)((lrow * 36 + lcol) * 4); \
        uint32_t bb = ab + 18432u;                                             \
        const float* ag = Ag + (size_t)lrow * lda + (k0) + lcol;               \
        const float* bg = Bg + (size_t)lrow * ldb + (k0) + lcol;               \
        cp16(ab,      ag);     cp16(ab + 16, ag + 4);                          \
        cp16(ab + 32, ag + 8); cp16(ab + 48, ag + 12);                         \
        cp16(bb,      bg);     cp16(bb + 16, bg + 4);                          \
        cp16(bb + 32, bg + 8); cp16(bb + 48, bg + 12);                         \
        cp_commit();                                                           \
    } while (0)

    NT_ISSUE(0, 0);
    if (nc > 1) NT_ISSUE(1, 32);

    for (int ch = 0; ch < nc; ch++) {
        if (ch + 1 < nc) cp_wait1(); else cp_wait0();
        __syncthreads();

        const float* As_ = dsm + (ch & 1) * 9216;
        const float* Bs_ = As_ + 4608;

        #pragma unroll
        for (int ks = 0; ks < 4; ks++) {
            const int kb = ks * 8 + q;
            uint32_t af[4][4], bf[4][2];
            #pragma unroll
            for (int mi = 0; mi < 4; mi++) {
                const int m0 = wm * 64 + mi * 16 + lr;
                af[mi][0] = f2tf32(As_[m0 * 36 + kb]);
                af[mi][1] = f2tf32(As_[(m0 + 8) * 36 + kb]);
                af[mi][2] = f2tf32(As_[m0 * 36 + kb + 4]);
                af[mi][3] = f2tf32(As_[(m0 + 8) * 36 + kb + 4]);
            }
            #pragma unroll
            for (int ni = 0; ni < 4; ni++) {
                const int n0 = wn * 32 + ni * 8 + lr;
                bf[ni][0] = f2tf32(Bs_[n0 * 36 + kb]);
                bf[ni][1] = f2tf32(Bs_[n0 * 36 + kb + 4]);
            }
            #pragma unroll
            for (int mi = 0; mi < 4; mi++)
                #pragma unroll
                for (int ni = 0; ni < 4; ni++)
                    mma_tf32(acc[mi][ni], af[mi], bf[ni]);
        }
        __syncthreads();
        if (ch + 2 < nc) NT_ISSUE((ch + 2) & 1, (ch + 2) * 32);
    }
    #undef NT_ISSUE

    float* stg = dsm;
    #pragma unroll
    for (int half = 0; half < 2; half++) {
        if (wm == half) {
            #pragma unroll
            for (int mi = 0; mi < 4; mi++) {
                const int rr = mi * 16 + lr;
                #pragma unroll
                for (int ni = 0; ni < 4; ni++) {
                    const int cc = wn * 32 + ni * 8 + q * 2;
                    stg[rr * 132 + cc]           = acc[mi][ni][0] * alpha;
                    stg[rr * 132 + cc + 1]       = acc[mi][ni][1] * alpha;
                    stg[(rr + 8) * 132 + cc]     = acc[mi][ni][2] * alpha;
                    stg[(rr + 8) * 132 + cc + 1] = acc[mi][ni][3] * alpha;
                }
            }
        }
        __syncthreads();
        #pragma unroll
        for (int i = 0; i < 8; i++) {
            const int row = (tid >> 5) * 8 + i;
            const int col = (tid & 31) * 4;
            *(float4*)&C[(size_t)(mBase + half * 64 + row) * ldc + nBase + col] =
                *(const float4*)&stg[row * 132 + col];
        }
        __syncthreads();
    }
}

// ---------------------------------------------------------------------------
__global__ __launch_bounds__(256, 2) void qkv_proj_kernel(
    const float* __restrict__ q, const float* __restrict__ k, const float* __restrict__ v,
    const float* __restrict__ Wq, const float* __restrict__ Wk, const float* __restrict__ Wv,
    float* __restrict__ qp, float* __restrict__ kp, float* __restrict__ vp)
{
    extern __shared__ float dsm[];
    const float* A; const float* B; float* C;
    if (blockIdx.z == 0)      { A = q; B = Wq; C = qp; }
    else if (blockIdx.z == 1) { A = k; B = Wk; C = kp; }
    else                      { A = v; B = Wv; C = vp; }
    gemm_nt_core(A, B, C, DMODEL, DMODEL, DMODEL, DMODEL, 1.f,
                 blockIdx.y * 128, blockIdx.x * 128, dsm);
}

__global__ __launch_bounds__(256, 2) void out_proj_kernel(
    const float* __restrict__ A, const float* __restrict__ B, float* __restrict__ C)
{
    extern __shared__ float dsm[];
    gemm_nt_core(A, B, C, DMODEL, DMODEL, DMODEL, DMODEL, 1.f,
                 blockIdx.y * 128, blockIdx.x * 128, dsm);
}

// ---------------------------------------------------------------------------
// Scores + exp: E = exp(0.125 * Q@K^T) (unnormalized) + Zp partial rowsums.
// BK=32, K=64 -> 2 chunks, 2 stages. Epilogue identical to R8.
// ---------------------------------------------------------------------------
__global__ __launch_bounds__(256, 2) void scores_exp_kernel(
    const float* __restrict__ qp, const float* __restrict__ kp,
    float* __restrict__ wts, float* __restrict__ Zp)
{
    extern __shared__ float dsm[];
    const int bh = blockIdx.z;
    const int b  = bh >> 4, h = bh & 15;
    const int ct = blockIdx.x;
    const int mBase = blockIdx.y * 128;
    const int nBase = ct * 128;

    const float* Ag = qp + (size_t)b * SEQ * DMODEL + h * DK + (size_t)mBase * DMODEL;
    const float* Bg = kp + (size_t)b * SEQ * DMODEL + h * DK + (size_t)nBase * DMODEL;
    float*       C  = wts + (size_t)bh * SEQ * SEQ;

    const int tid  = threadIdx.x;
    const int lane = tid & 31;
    const int warp = tid >> 5;
    const int wm   = warp >> 2;
    const int wn   = warp & 3;
    const int q    = lane & 3;
    const int lr   = lane >> 2;
    const int lrow = tid >> 1;
    const int lcol = (tid & 1) * 16;

    const uint32_t sbase = (uint32_t)__cvta_generic_to_shared(dsm);

    float acc[4][4][4];
    #pragma unroll
    for (int i = 0; i < 4; i++)
        #pragma unroll
        for (int j = 0; j < 4; j++)
            #pragma unroll
            for (int t = 0; t < 4; t++) acc[i][j][t] = 0.f;

    #define SC_ISSUE(st, k0) do {                                              \
        uint32_t ab = sbase + (st) * 36864u + (uint32_t)((lrow * 36 + lcol) * 4); \
        uint32_t bb = ab + 18432u;                                             \
        const float* ag = Ag + (size_t)lrow * DMODEL + (k0) + lcol;            \
        const float* bg = Bg + (size_t)lrow * DMODEL + (k0) + lcol;            \
        cp16(ab,      ag);     cp16(ab + 16, ag + 4);                          \
        cp16(ab + 32, ag + 8); cp16(ab + 48, ag + 12);                         \
        cp16(bb,      bg);     cp16(bb + 16, bg + 4);                          \
        cp16(bb + 32, bg + 8); cp16(bb + 48, bg + 12);                         \
        cp_commit();                                                           \
    } while (0)

    const int nc = DK >> 5;   // 2
    SC_ISSUE(0, 0);
    SC_ISSUE(1, 32);

    for (int ch = 0; ch < nc; ch++) {
        if (ch + 1 < nc) cp_wait1(); else cp_wait0();
        __syncthreads();

        const float* As_ = dsm + (ch & 1) * 9216;
        const float* Bs_ = As_ + 4608;

        #pragma unroll
        for (int ks = 0; ks < 4; ks++) {
            const int kb = ks * 8 + q;
            uint32_t af[4][4], bf[4][2];
            #pragma unroll
            for (int mi = 0; mi < 4; mi++) {
                const int m0 = wm * 64 + mi * 16 + lr;
                af[mi][0] = f2tf32(As_[m0 * 36 + kb]);
                af[mi][1] = f2tf32(As_[(m0 + 8) * 36 + kb]);
                af[mi][2] = f2tf32(As_[m0 * 36 + kb + 4]);
                af[mi][3] = f2tf32(As_[(m0 + 8) * 36 + kb + 4]);
            }
            #pragma unroll
            for (int ni = 0; ni < 4; ni++) {
                const int n0 = wn * 32 + ni * 8 + lr;
                bf[ni][0] = f2tf32(Bs_[n0 * 36 + kb]);
                bf[ni][1] = f2tf32(Bs_[n0 * 36 + kb + 4]);
            }
            #pragma unroll
            for (int mi = 0; mi < 4; mi++)
                #pragma unroll
                for (int ni = 0; ni < 4; ni++)
                    mma_tf32(acc[mi][ni], af[mi], bf[ni]);
        }
        __syncthreads();
    }
    #undef SC_ISSUE

    // Epilogue: exp, partial rowsums, coalesced E store
    float* stg = dsm;
    #pragma unroll
    for (int half = 0; half < 2; half++) {
        if (wm == half) {
            #pragma unroll
            for (int mi = 0; mi < 4; mi++) {
                const int rr = mi * 16 + lr;
                #pragma unroll
                for (int ni = 0; ni < 4; ni++) {
                    const int cc = wn * 32 + ni * 8 + q * 2;
                    stg[rr * 132 + cc]           = fast_exp(0.125f * acc[mi][ni][0]);
                    stg[rr * 132 + cc + 1]       = fast_exp(0.125f * acc[mi][ni][1]);
                    stg[(rr + 8) * 132 + cc]     = fast_exp(0.125f * acc[mi][ni][2]);
                    stg[(rr + 8) * 132 + cc + 1] = fast_exp(0.125f * acc[mi][ni][3]);
                }
            }
        }
        __syncthreads();
        {
            const int row = tid >> 2;
            const int seg = tid & 3;
            const float* rp = &stg[row * 132 + seg * 32];
            float s = 0.f;
            #pragma unroll
            for (int j = 0; j < 32; j++) s += rp[j];
            s += __shfl_xor_sync(0xFFFFFFFFu, s, 1);
            s += __shfl_xor_sync(0xFFFFFFFFu, s, 2);
            if (seg == 0)
                Zp[((size_t)(bh * 16 + ct)) * 2048 + mBase + half * 64 + row] = s;
        }
        #pragma unroll
        for (int i = 0; i < 8; i++) {
            const int row = (tid >> 5) * 8 + i;
            const int col = (tid & 31) * 4;
            *(float4*)&C[(size_t)(mBase + half * 64 + row) * SEQ + nBase + col] =
                *(const float4*)&stg[row * 132 + col];
        }
        __syncthreads();
    }
}

// ---------------------------------------------------------------------------
// PV + normalize, BK=32: reads E, computes invZ from Zp, writes P = E*invZ
// back in-place in FULL 128B row segments, O = (E@V)*invZ.
// Stage = As[128][36] (4608) + Bs[32][72] (2304) = 6912 floats; 3 stages.
// ---------------------------------------------------------------------------
__global__ __launch_bounds__(256, 2) void pv_norm_kernel(
    float* __restrict__ P, const float* __restrict__ V, float* __restrict__ C,
    const float* __restrict__ Zp)
{
    extern __shared__ float dsm[];
    __shared__ float invz[128];

    const int z = blockIdx.z;
    const int b = z >> 4, h = z & 15;
    const int mBase = blockIdx.y * 128;

    float*       Ag = P + (size_t)z * SEQ * SEQ + (size_t)mBase * SEQ;
    const float* Bg = V + (size_t)b * SEQ * DMODEL + h * DK;
    float*       Cg = C + (size_t)b * SEQ * DMODEL + h * DK + (size_t)mBase * DMODEL;

    const int tid  = threadIdx.x;
    const int lane = tid & 31;
    const int warp = tid >> 5;
    const int wm   = warp >> 1;
    const int wn   = warp & 1;
    const int q    = lane & 3;
    const int lr   = lane >> 2;
    const int lrow = tid >> 1;           // A loader: 0..127
    const int lcol = (tid & 1) * 16;
    const int kr   = tid >> 3;           // B loader: k row 0..31
    const int ncf  = (tid & 7) * 8;      // B loader: col floats 0..56

    if (tid < 128) {
        float s = 0.f;
        #pragma unroll
        for (int t = 0; t < 16; t++)
            s += Zp[((size_t)(z * 16 + t)) * 2048 + mBase + tid];
        invz[tid] = 1.f / s;
    }

    const uint32_t sbase = (uint32_t)__cvta_generic_to_shared(dsm);

    float acc[2][4][4];
    #pragma unroll
    for (int i = 0; i < 2; i++)
        #pragma unroll
        for (int j = 0; j < 4; j++)
            #pragma unroll
            for (int t = 0; t < 4; t++) acc[i][j][t] = 0.f;

    #define PV_ISSUE(st, k0) do {                                               \
        uint32_t ab = sbase + (st) * 27648u + (uint32_t)((lrow * 36 + lcol) * 4); \
        uint32_t bb = sbase + (st) * 27648u + 18432u + (uint32_t)((kr * 72 + ncf) * 4); \
        const float* ag = Ag + (size_t)lrow * SEQ + (k0) + lcol;                \
        const float* bg = Bg + (size_t)((k0) + kr) * DMODEL + ncf;              \
        cp16(ab,      ag);     cp16(ab + 16, ag + 4);                           \
        cp16(ab + 32, ag + 8); cp16(ab + 48, ag + 12);                          \
        cp16(bb, bg);          cp16(bb + 16, bg + 4);                           \
        cp_commit();                                                            \
    } while (0)

    const int nc = SEQ >> 5;   // 64
    PV_ISSUE(0, 0);
    PV_ISSUE(1, 32);
    __syncthreads();   // invz visible before writeback use

    for (int ch = 0; ch < nc; ch++) {
        if (ch + 1 < nc) cp_wait1(); else cp_wait0();
        __syncthreads();

        const float* As_ = dsm + (ch % 3) * 6912;
        const float* Bs_ = As_ + 4608;

        #pragma unroll
        for (int ks = 0; ks < 4; ks++) {
            const int kb = ks * 8 + q;
            uint32_t af[2][4], bf[4][2];
            #pragma unroll
            for (int mi = 0; mi < 2; mi++) {
                const int m0 = wm * 32 + mi * 16 + lr;
                af[mi][0] = f2tf32(As_[m0 * 36 + kb]);
                af[mi][1] = f2tf32(As_[(m0 + 8) * 36 + kb]);
                af[mi][2] = f2tf32(As_[m0 * 36 + kb + 4]);
                af[mi][3] = f2tf32(As_[(m0 + 8) * 36 + kb + 4]);
            }
            #pragma unroll
            for (int ni = 0; ni < 4; ni++) {
                const int n0 = wn * 32 + ni * 8 + lr;
                bf[ni][0] = f2tf32(Bs_[kb * 72 + n0]);
                bf[ni][1] = f2tf32(Bs_[(kb + 4) * 72 + n0]);
            }
            #pragma unroll
            for (int mi = 0; mi < 2; mi++)
                #pragma unroll
                for (int ni = 0; ni < 4; ni++)
                    mma_tf32(acc[mi][ni], af[mi], bf[ni]);
        }

        // write normalized P for this 32-col chunk: 128B contiguous per row
        #pragma unroll
        for (int i = 0; i < 4; i++) {
            const int idx = tid + 256 * i;          // 0..1023
            const int row = idx >> 3;
            const int cc  = (idx & 7) << 2;
            const float* src = &As_[row * 36 + cc];
            const float iz = invz[row];
            float4 o = make_float4(src[0] * iz, src[1] * iz, src[2] * iz, src[3] * iz);
            *(float4*)&Ag[(size_t)row * SEQ + ch * 32 + cc] = o;
        }

        __syncthreads();
        if (ch + 2 < nc) PV_ISSUE((ch + 2) % 3, (ch + 2) * 32);
    }
    #undef PV_ISSUE

    // staged epilogue, O scaled by invZ
    float* stg = dsm;
    #pragma unroll
    for (int mi = 0; mi < 2; mi++) {
        const int rr = wm * 32 + mi * 16 + lr;
        #pragma unroll
        for (int ni = 0; ni < 4; ni++) {
            const int cc = wn * 32 + ni * 8 + q * 2;
            stg[rr * 68 + cc]           = acc[mi][ni][0] * invz[rr];
            stg[rr * 68 + cc + 1]       = acc[mi][ni][1] * invz[rr];
            stg[(rr + 8) * 68 + cc]     = acc[mi][ni][2] * invz[rr + 8];
            stg[(rr + 8) * 68 + cc + 1] = acc[mi][ni][3] * invz[rr + 8];
        }
    }
    __syncthreads();
    #pragma unroll
    for (int i = 0; i < 8; i++) {
        const int row = (tid >> 4) * 8 + i;
        const int col = (tid & 15) * 4;
        *(float4*)&Cg[(size_t)row * DMODEL + col] = *(const float4*)&stg[row * 68 + col];
    }
}

// ---------------------------------------------------------------------------
extern "C" void kernel_launch(void* const* d_in, const int* in_sizes, int n_in,
                              void* d_out, int out_size)
{
    const float* q  = (const float*)d_in[0];
    const float* k  = (const float*)d_in[1];
    const float* v  = (const float*)d_in[2];
    const float* Wq = (const float*)d_in[3];
    const float* Wk = (const float*)d_in[4];
    const float* Wv = (const float*)d_in[5];
    const float* Wo = (const float*)d_in[6];
    float* out = (float*)d_out;
    float* wts = out + OUT_OFF;

    float *qp, *kp, *vp, *ao, *zp;
    cudaGetSymbolAddress((void**)&qp, g_qp);
    cudaGetSymbolAddress((void**)&kp, g_kp);
    cudaGetSymbolAddress((void**)&vp, g_vp);
    cudaGetSymbolAddress((void**)&ao, g_ao);
    cudaGetSymbolAddress((void**)&zp, g_zp);

    const int NT_DSM = 2 * 36864;   // 73728 B
    const int PV_DSM = 3 * 27648;   // 82944 B
    cudaFuncSetAttribute(qkv_proj_kernel,   cudaFuncAttributeMaxDynamicSharedMemorySize, NT_DSM);
    cudaFuncSetAttribute(scores_exp_kernel, cudaFuncAttributeMaxDynamicSharedMemorySize, NT_DSM);
    cudaFuncSetAttribute(out_proj_kernel,   cudaFuncAttributeMaxDynamicSharedMemorySize, NT_DSM);
    cudaFuncSetAttribute(pv_norm_kernel,    cudaFuncAttributeMaxDynamicSharedMemorySize, PV_DSM);

    const dim3 thr(256);

    // Q/K/V projections
    qkv_proj_kernel<<<dim3(8, 32, 3), thr, NT_DSM>>>(q, k, v, Wq, Wk, Wv, qp, kp, vp);

    // Scores + exp -> E (unnormalized) + Z partials
    scores_exp_kernel<<<dim3(16, 16, 32), thr, NT_DSM>>>(qp, kp, wts, zp);

    // P@V with coalesced in-place normalization of P and O rescale
    pv_norm_kernel<<<dim3(1, 16, 32), thr, PV_DSM>>>(wts, vp, ao, zp);

    // Output projection
    out_proj_kernel<<<dim3(8, 32, 1), thr, NT_DSM>>>(ao, Wo, out);
}

// round 10
// speedup vs baseline: 1.2526x; 1.2526x over previous
#include <cuda_runtime.h>
#include <stdint.h>
#include <math.h>

#define BATCH   2
#define SEQ     2048
#define DMODEL  1024
#define NHEAD   16
#define DK      64
#define MTOT    (BATCH*SEQ)
#define OUT_OFF ((size_t)MTOT*DMODEL)

// Scratch: projections (stored tf32-rounded) and attention output
__device__ float g_qp[MTOT*DMODEL];
__device__ float g_kp[MTOT*DMODEL];
__device__ float g_vp[MTOT*DMODEL];
__device__ float g_ao[MTOT*DMODEL];

// ---------------------------------------------------------------------------
__device__ __forceinline__ uint32_t f2tf32(float x) {
    uint32_t u;
    asm("cvt.rna.tf32.f32 %0, %1;" : "=r"(u) : "f"(x));
    return u;
}

template<bool CVT>
__device__ __forceinline__ uint32_t frag(float x) {
    return CVT ? f2tf32(x) : __float_as_uint(x);
}

__device__ __forceinline__ void mma_tf32(float* d, const uint32_t* a, const uint32_t* b) {
    asm volatile(
        "mma.sync.aligned.m16n8k8.row.col.f32.tf32.tf32.f32 "
        "{%0,%1,%2,%3}, {%4,%5,%6,%7}, {%8,%9}, {%0,%1,%2,%3};"
        : "+f"(d[0]), "+f"(d[1]), "+f"(d[2]), "+f"(d[3])
        : "r"(a[0]), "r"(a[1]), "r"(a[2]), "r"(a[3]), "r"(b[0]), "r"(b[1]));
}

__device__ __forceinline__ void cp16(uint32_t saddr, const void* gptr) {
    asm volatile("cp.async.cg.shared.global [%0], [%1], 16;" :: "r"(saddr), "l"(gptr));
}
__device__ __forceinline__ void cp_commit() { asm volatile("cp.async.commit_group;"); }
__device__ __forceinline__ void cp_wait1()  { asm volatile("cp.async.wait_group 1;"); }
__device__ __forceinline__ void cp_wait0()  { asm volatile("cp.async.wait_group 0;"); }

// ---------------------------------------------------------------------------
// NT core: C[128x128 tile] = alpha * A @ B^T. BK=16, 3-stage cp.async.
// CVTA/CVTB: round that operand to tf32 at fragment load (skip if the
// producer already stored tf32-rounded values). CVTO: round output at store.
// ---------------------------------------------------------------------------
template<bool CVTA, bool CVTB, bool CVTO>
__device__ __forceinline__ void gemm_nt_core(
    const float* __restrict__ A, const float* __restrict__ B, float* __restrict__ C,
    int K, int lda, int ldb, int ldc, float alpha,
    int mBase, int nBase, float* dsm)
{
    const int tid  = threadIdx.x;
    const int lane = tid & 31;
    const int warp = tid >> 5;
    const int wm   = warp >> 2;
    const int wn   = warp & 3;
    const int q    = lane & 3;
    const int lr   = lane >> 2;
    const int r0   = tid >> 2;
    const int c4   = (tid & 3) << 2;

    const uint32_t sbase = (uint32_t)__cvta_generic_to_shared(dsm);
    const float* Ag = A + (size_t)mBase * lda;
    const float* Bg = B + (size_t)nBase * ldb;

    float acc[4][4][4];
    #pragma unroll
    for (int i = 0; i < 4; i++)
        #pragma unroll
        for (int j = 0; j < 4; j++)
            #pragma unroll
            for (int t = 0; t < 4; t++) acc[i][j][t] = 0.f;

    const int nc = K >> 4;

    #define NT_ISSUE(st, k0) do {                                              \
        uint32_t ab = sbase + (st) * 20480u + (uint32_t)(r0 * 80 + c4 * 4);    \
        uint32_t bb = ab + 10240u;                                             \
        cp16(ab,          Ag + (size_t)r0 * lda + (k0) + c4);                  \
        cp16(ab + 5120u,  Ag + (size_t)(r0 + 64) * lda + (k0) + c4);           \
        cp16(bb,          Bg + (size_t)r0 * ldb + (k0) + c4);                  \
        cp16(bb + 5120u,  Bg + (size_t)(r0 + 64) * ldb + (k0) + c4);           \
        cp_commit();                                                           \
    } while (0)

    NT_ISSUE(0, 0);
    if (nc > 1) NT_ISSUE(1, 16);

    for (int ch = 0; ch < nc; ch++) {
        if (ch + 1 < nc) cp_wait1(); else cp_wait0();
        __syncthreads();

        const float* As_ = dsm + (ch % 3) * 5120;
        const float* Bs_ = As_ + 2560;

        #pragma unroll
        for (int ks = 0; ks < 2; ks++) {
            const int kb = ks * 8 + q;
            uint32_t af[4][4], bf[4][2];
            #pragma unroll
            for (int mi = 0; mi < 4; mi++) {
                const int m0 = wm * 64 + mi * 16 + lr;
                af[mi][0] = frag<CVTA>(As_[m0 * 20 + kb]);
                af[mi][1] = frag<CVTA>(As_[(m0 + 8) * 20 + kb]);
                af[mi][2] = frag<CVTA>(As_[m0 * 20 + kb + 4]);
                af[mi][3] = frag<CVTA>(As_[(m0 + 8) * 20 + kb + 4]);
            }
            #pragma unroll
            for (int ni = 0; ni < 4; ni++) {
                const int n0 = wn * 32 + ni * 8 + lr;
                bf[ni][0] = frag<CVTB>(Bs_[n0 * 20 + kb]);
                bf[ni][1] = frag<CVTB>(Bs_[n0 * 20 + kb + 4]);
            }
            #pragma unroll
            for (int mi = 0; mi < 4; mi++)
                #pragma unroll
                for (int ni = 0; ni < 4; ni++)
                    mma_tf32(acc[mi][ni], af[mi], bf[ni]);
        }
        __syncthreads();
        if (ch + 2 < nc) NT_ISSUE((ch + 2) % 3, (ch + 2) * 16);
    }
    #undef NT_ISSUE

    // staged epilogue: two 64x128 halves through smem
    float* stg = dsm;
    #pragma unroll
    for (int half = 0; half < 2; half++) {
        if (wm == half) {
            #pragma unroll
            for (int mi = 0; mi < 4; mi++) {
                const int rr = mi * 16 + lr;
                #pragma unroll
                for (int ni = 0; ni < 4; ni++) {
                    const int cc = wn * 32 + ni * 8 + q * 2;
                    float v0 = acc[mi][ni][0] * alpha, v1 = acc[mi][ni][1] * alpha;
                    float v2 = acc[mi][ni][2] * alpha, v3 = acc[mi][ni][3] * alpha;
                    if (CVTO) {
                        v0 = __uint_as_float(f2tf32(v0));
                        v1 = __uint_as_float(f2tf32(v1));
                        v2 = __uint_as_float(f2tf32(v2));
                        v3 = __uint_as_float(f2tf32(v3));
                    }
                    stg[rr * 132 + cc]           = v0;
                    stg[rr * 132 + cc + 1]       = v1;
                    stg[(rr + 8) * 132 + cc]     = v2;
                    stg[(rr + 8) * 132 + cc + 1] = v3;
                }
            }
        }
        __syncthreads();
        #pragma unroll
        for (int i = 0; i < 8; i++) {
            const int row = (tid >> 5) * 8 + i;
            const int col = (tid & 31) * 4;
            *(float4*)&C[(size_t)(mBase + half * 64 + row) * ldc + nBase + col] =
                *(const float4*)&stg[row * 132 + col];
        }
        __syncthreads();
    }
}

// ---------------------------------------------------------------------------
__global__ __launch_bounds__(256, 2) void qkv_proj_kernel(
    const float* __restrict__ q, const float* __restrict__ k, const float* __restrict__ v,
    const float* __restrict__ Wq, const float* __restrict__ Wk, const float* __restrict__ Wv,
    float* __restrict__ qp, float* __restrict__ kp, float* __restrict__ vp)
{
    extern __shared__ float dsm[];
    const float* A; const float* B; float* C;
    if (blockIdx.z == 0)      { A = q; B = Wq; C = qp; }
    else if (blockIdx.z == 1) { A = k; B = Wk; C = kp; }
    else                      { A = v; B = Wv; C = vp; }
    // raw inputs -> cvt both; outputs stored tf32-rounded
    gemm_nt_core<true, true, true>(A, B, C, DMODEL, DMODEL, DMODEL, DMODEL, 1.f,
                                   blockIdx.y * 128, blockIdx.x * 128, dsm);
}

__global__ __launch_bounds__(256, 2) void out_proj_kernel(
    const float* __restrict__ A, const float* __restrict__ B, float* __restrict__ C)
{
    extern __shared__ float dsm[];
    // A = ao (pre-rounded), B = Wo (raw) -> cvt B only; output raw fp32
    gemm_nt_core<false, true, false>(A, B, C, DMODEL, DMODEL, DMODEL, DMODEL, 1.f,
                                     blockIdx.y * 128, blockIdx.x * 128, dsm);
}

__global__ __launch_bounds__(256, 2) void scores_kernel(
    const float* __restrict__ qp, const float* __restrict__ kp, float* __restrict__ wts)
{
    extern __shared__ float dsm[];
    const int bh = blockIdx.z;
    const int b = bh >> 4, h = bh & 15;
    const float* A = qp + (size_t)b * SEQ * DMODEL + h * DK;
    const float* B = kp + (size_t)b * SEQ * DMODEL + h * DK;
    float*       C = wts + (size_t)bh * SEQ * SEQ;
    // both operands pre-rounded -> no in-loop cvt
    gemm_nt_core<false, false, false>(A, B, C, DK, DMODEL, DMODEL, SEQ, 0.125f,
                                      blockIdx.y * 128, blockIdx.x * 128, dsm);
}

// ---------------------------------------------------------------------------
// Row softmax, in place, float4 path: 65536 rows of 2048.
// ---------------------------------------------------------------------------
__global__ __launch_bounds__(256) void softmax_kernel(float* __restrict__ Wt)
{
    float4* row4 = (float4*)(Wt + (size_t)blockIdx.x * SEQ);
    const int tid = threadIdx.x;
    __shared__ float red[8];

    float4 a = row4[tid];
    float4 b = row4[tid + 256];

    float m = fmaxf(fmaxf(fmaxf(a.x, a.y), fmaxf(a.z, a.w)),
                    fmaxf(fmaxf(b.x, b.y), fmaxf(b.z, b.w)));
    #pragma unroll
    for (int o = 16; o; o >>= 1) m = fmaxf(m, __shfl_xor_sync(0xFFFFFFFFu, m, o));
    if ((tid & 31) == 0) red[tid >> 5] = m;
    __syncthreads();
    m = red[0];
    #pragma unroll
    for (int i = 1; i < 8; i++) m = fmaxf(m, red[i]);
    __syncthreads();

    a.x = __expf(a.x - m); a.y = __expf(a.y - m);
    a.z = __expf(a.z - m); a.w = __expf(a.w - m);
    b.x = __expf(b.x - m); b.y = __expf(b.y - m);
    b.z = __expf(b.z - m); b.w = __expf(b.w - m);

    float s = a.x + a.y + a.z + a.w + b.x + b.y + b.z + b.w;
    #pragma unroll
    for (int o = 16; o; o >>= 1) s += __shfl_xor_sync(0xFFFFFFFFu, s, o);
    if ((tid & 31) == 0) red[tid >> 5] = s;
    __syncthreads();
    s = red[0];
    #pragma unroll
    for (int i = 1; i < 8; i++) s += red[i];
    const float inv = 1.f / s;

    a.x *= inv; a.y *= inv; a.z *= inv; a.w *= inv;
    b.x *= inv; b.y *= inv; b.z *= inv; b.w *= inv;
    row4[tid]       = a;
    row4[tid + 256] = b;
}

// ---------------------------------------------------------------------------
// PV: C[128,64] tiles = P @ V. 3-stage cp.async. P needs cvt (fp32 softmax
// values); V pre-rounded. Output ao stored tf32-rounded (feeds out-proj MMA).
// ---------------------------------------------------------------------------
__global__ __launch_bounds__(256, 2) void pv_async_kernel(
    const float* __restrict__ P, const float* __restrict__ V, float* __restrict__ C)
{
    __shared__ float sm[3 * 3712];

    const int z = blockIdx.z;
    const int b = z >> 4, h = z & 15;
    const int mBase = blockIdx.y * 128;

    const float* Ag = P + (size_t)z * SEQ * SEQ + (size_t)mBase * SEQ;
    const float* Bg = V + (size_t)b * SEQ * DMODEL + h * DK;
    float*       Cg = C + (size_t)b * SEQ * DMODEL + h * DK + (size_t)mBase * DMODEL;

    const int tid  = threadIdx.x;
    const int lane = tid & 31;
    const int warp = tid >> 5;
    const int wm   = warp >> 1;
    const int wn   = warp & 1;
    const int q    = lane & 3;
    const int lr   = lane >> 2;
    const int r0   = tid >> 2;
    const int c4   = (tid & 3) << 2;
    const int kr   = tid >> 4;
    const int n4   = (tid & 15) << 2;

    const uint32_t sbase = (uint32_t)__cvta_generic_to_shared(sm);

    float acc[2][4][4];
    #pragma unroll
    for (int i = 0; i < 2; i++)
        #pragma unroll
        for (int j = 0; j < 4; j++)
            #pragma unroll
            for (int t = 0; t < 4; t++) acc[i][j][t] = 0.f;

    #define PV_ISSUE(st, k0) do {                                               \
        uint32_t ab = sbase + (st) * 14848u + (uint32_t)(r0 * 80 + c4 * 4);     \
        uint32_t bb = sbase + (st) * 14848u + 10240u + (uint32_t)(kr * 288 + n4 * 4); \
        cp16(ab,         Ag + (size_t)r0 * SEQ + (k0) + c4);                    \
        cp16(ab + 5120u, Ag + (size_t)(r0 + 64) * SEQ + (k0) + c4);             \
        cp16(bb,         Bg + (size_t)((k0) + kr) * DMODEL + n4);               \
        cp_commit();                                                            \
    } while (0)

    const int nc = SEQ >> 4;
    PV_ISSUE(0, 0);
    PV_ISSUE(1, 16);

    for (int ch = 0; ch < nc; ch++) {
        if (ch + 1 < nc) cp_wait1(); else cp_wait0();
        __syncthreads();

        const float* As_ = sm + (ch % 3) * 3712;
        const float* Bs_ = As_ + 2560;

        #pragma unroll
        for (int ks = 0; ks < 2; ks++) {
            const int kb = ks * 8 + q;
            uint32_t af[2][4], bf[4][2];
            #pragma unroll
            for (int mi = 0; mi < 2; mi++) {
                const int m0 = wm * 32 + mi * 16 + lr;
                af[mi][0] = f2tf32(As_[m0 * 20 + kb]);
                af[mi][1] = f2tf32(As_[(m0 + 8) * 20 + kb]);
                af[mi][2] = f2tf32(As_[m0 * 20 + kb + 4]);
                af[mi][3] = f2tf32(As_[(m0 + 8) * 20 + kb + 4]);
            }
            #pragma unroll
            for (int ni = 0; ni < 4; ni++) {
                const int n0 = wn * 32 + ni * 8 + lr;
                bf[ni][0] = __float_as_uint(Bs_[kb * 72 + n0]);
                bf[ni][1] = __float_as_uint(Bs_[(kb + 4) * 72 + n0]);
            }
            #pragma unroll
            for (int mi = 0; mi < 2; mi++)
                #pragma unroll
                for (int ni = 0; ni < 4; ni++)
                    mma_tf32(acc[mi][ni], af[mi], bf[ni]);
        }
        __syncthreads();
        if (ch + 2 < nc) PV_ISSUE((ch + 2) % 3, (ch + 2) * 16);
    }
    #undef PV_ISSUE

    // staged epilogue (output tf32-rounded; consumed only by out-proj MMA)
    float* stg = sm;
    #pragma unroll
    for (int mi = 0; mi < 2; mi++) {
        const int rr = wm * 32 + mi * 16 + lr;
        #pragma unroll
        for (int ni = 0; ni < 4; ni++) {
            const int cc = wn * 32 + ni * 8 + q * 2;
            stg[rr * 68 + cc]           = __uint_as_float(f2tf32(acc[mi][ni][0]));
            stg[rr * 68 + cc + 1]       = __uint_as_float(f2tf32(acc[mi][ni][1]));
            stg[(rr + 8) * 68 + cc]     = __uint_as_float(f2tf32(acc[mi][ni][2]));
            stg[(rr + 8) * 68 + cc + 1] = __uint_as_float(f2tf32(acc[mi][ni][3]));
        }
    }
    __syncthreads();
    #pragma unroll
    for (int i = 0; i < 8; i++) {
        const int row = (tid >> 4) * 8 + i;
        const int col = (tid & 15) * 4;
        *(float4*)&Cg[(size_t)row * DMODEL + col] = *(const float4*)&stg[row * 68 + col];
    }
}

// ---------------------------------------------------------------------------
extern "C" void kernel_launch(void* const* d_in, const int* in_sizes, int n_in,
                              void* d_out, int out_size)
{
    const float* q  = (const float*)d_in[0];
    const float* k  = (const float*)d_in[1];
    const float* v  = (const float*)d_in[2];
    const float* Wq = (const float*)d_in[3];
    const float* Wk = (const float*)d_in[4];
    const float* Wv = (const float*)d_in[5];
    const float* Wo = (const float*)d_in[6];
    float* out = (float*)d_out;
    float* wts = out + OUT_OFF;

    float *qp, *kp, *vp, *ao;
    cudaGetSymbolAddress((void**)&qp, g_qp);
    cudaGetSymbolAddress((void**)&kp, g_kp);
    cudaGetSymbolAddress((void**)&vp, g_vp);
    cudaGetSymbolAddress((void**)&ao, g_ao);

    const int DSM = 3 * 20480;  // 61440 bytes
    cudaFuncSetAttribute(qkv_proj_kernel, cudaFuncAttributeMaxDynamicSharedMemorySize, DSM);
    cudaFuncSetAttribute(scores_kernel,  cudaFuncAttributeMaxDynamicSharedMemorySize, DSM);
    cudaFuncSetAttribute(out_proj_kernel, cudaFuncAttributeMaxDynamicSharedMemorySize, DSM);

    const dim3 thr(256);

    // Q/K/V projections in one launch (outputs tf32-rounded)
    qkv_proj_kernel<<<dim3(8, 32, 3), thr, DSM>>>(q, k, v, Wq, Wk, Wv, qp, kp, vp);

    // Scores: per (b,h) Qh @ Kh^T * 0.125 (no in-loop cvt)
    scores_kernel<<<dim3(16, 16, 32), thr, DSM>>>(qp, kp, wts);

    // Softmax in place
    softmax_kernel<<<BATCH * NHEAD * SEQ, 256>>>(wts);

    // P @ V -> attn_out (stored tf32-rounded)
    pv_async_kernel<<<dim3(1, 16, 32), thr>>>(wts, vp, ao);

    // Output projection
    out_proj_kernel<<<dim3(8, 32, 1), thr, DSM>>>(ao, Wo, out);
}

// round 11
// speedup vs baseline: 1.2901x; 1.0300x over previous
#include <cuda_runtime.h>
#include <stdint.h>
#include <math.h>

#define BATCH   2
#define SEQ     2048
#define DMODEL  1024
#define NHEAD   16
#define DK      64
#define MTOT    (BATCH*SEQ)
#define OUT_OFF ((size_t)MTOT*DMODEL)

// Scratch: projections (stored tf32-rounded) and attention output
__device__ float g_qp[MTOT*DMODEL];
__device__ float g_kp[MTOT*DMODEL];
__device__ float g_vp[MTOT*DMODEL];
__device__ float g_ao[MTOT*DMODEL];

// ---------------------------------------------------------------------------
__device__ __forceinline__ uint32_t f2tf32(float x) {
    uint32_t u;
    asm("cvt.rna.tf32.f32 %0, %1;" : "=r"(u) : "f"(x));
    return u;
}

template<bool CVT>
__device__ __forceinline__ uint32_t frag(float x) {
    return CVT ? f2tf32(x) : __float_as_uint(x);
}

__device__ __forceinline__ void mma_tf32(float* d, const uint32_t* a, const uint32_t* b) {
    asm volatile(
        "mma.sync.aligned.m16n8k8.row.col.f32.tf32.tf32.f32 "
        "{%0,%1,%2,%3}, {%4,%5,%6,%7}, {%8,%9}, {%0,%1,%2,%3};"
        : "+f"(d[0]), "+f"(d[1]), "+f"(d[2]), "+f"(d[3])
        : "r"(a[0]), "r"(a[1]), "r"(a[2]), "r"(a[3]), "r"(b[0]), "r"(b[1]));
}

__device__ __forceinline__ void cp16(uint32_t saddr, const void* gptr) {
    asm volatile("cp.async.cg.shared.global [%0], [%1], 16;" :: "r"(saddr), "l"(gptr));
}
__device__ __forceinline__ void cp_commit() { asm volatile("cp.async.commit_group;"); }
__device__ __forceinline__ void cp_wait2()  { asm volatile("cp.async.wait_group 2;"); }
__device__ __forceinline__ void cp_wait1()  { asm volatile("cp.async.wait_group 1;"); }
__device__ __forceinline__ void cp_wait0()  { asm volatile("cp.async.wait_group 0;"); }

// ---------------------------------------------------------------------------
// NT core: C[128x128 tile] = alpha * A @ B^T. BK=16, 3-stage cp.async.
// CVTA/CVTB: round operand at fragment load; CVTO: round output at store.
// ---------------------------------------------------------------------------
template<bool CVTA, bool CVTB, bool CVTO>
__device__ __forceinline__ void gemm_nt_core(
    const float* __restrict__ A, const float* __restrict__ B, float* __restrict__ C,
    int K, int lda, int ldb, int ldc, float alpha,
    int mBase, int nBase, float* dsm)
{
    const int tid  = threadIdx.x;
    const int lane = tid & 31;
    const int warp = tid >> 5;
    const int wm   = warp >> 2;
    const int wn   = warp & 3;
    const int q    = lane & 3;
    const int lr   = lane >> 2;
    const int r0   = tid >> 2;
    const int c4   = (tid & 3) << 2;

    const uint32_t sbase = (uint32_t)__cvta_generic_to_shared(dsm);
    const float* Ag = A + (size_t)mBase * lda;
    const float* Bg = B + (size_t)nBase * ldb;

    float acc[4][4][4];
    #pragma unroll
    for (int i = 0; i < 4; i++)
        #pragma unroll
        for (int j = 0; j < 4; j++)
            #pragma unroll
            for (int t = 0; t < 4; t++) acc[i][j][t] = 0.f;

    const int nc = K >> 4;

    #define NT_ISSUE(st, k0) do {                                              \
        uint32_t ab = sbase + (st) * 20480u + (uint32_t)(r0 * 80 + c4 * 4);    \
        uint32_t bb = ab + 10240u;                                             \
        cp16(ab,          Ag + (size_t)r0 * lda + (k0) + c4);                  \
        cp16(ab + 5120u,  Ag + (size_t)(r0 + 64) * lda + (k0) + c4);           \
        cp16(bb,          Bg + (size_t)r0 * ldb + (k0) + c4);                  \
        cp16(bb + 5120u,  Bg + (size_t)(r0 + 64) * ldb + (k0) + c4);           \
        cp_commit();                                                           \
    } while (0)

    NT_ISSUE(0, 0);
    if (nc > 1) NT_ISSUE(1, 16);

    for (int ch = 0; ch < nc; ch++) {
        if (ch + 1 < nc) cp_wait1(); else cp_wait0();
        __syncthreads();

        const float* As_ = dsm + (ch % 3) * 5120;
        const float* Bs_ = As_ + 2560;

        #pragma unroll
        for (int ks = 0; ks < 2; ks++) {
            const int kb = ks * 8 + q;
            uint32_t af[4][4], bf[4][2];
            #pragma unroll
            for (int mi = 0; mi < 4; mi++) {
                const int m0 = wm * 64 + mi * 16 + lr;
                af[mi][0] = frag<CVTA>(As_[m0 * 20 + kb]);
                af[mi][1] = frag<CVTA>(As_[(m0 + 8) * 20 + kb]);
                af[mi][2] = frag<CVTA>(As_[m0 * 20 + kb + 4]);
                af[mi][3] = frag<CVTA>(As_[(m0 + 8) * 20 + kb + 4]);
            }
            #pragma unroll
            for (int ni = 0; ni < 4; ni++) {
                const int n0 = wn * 32 + ni * 8 + lr;
                bf[ni][0] = frag<CVTB>(Bs_[n0 * 20 + kb]);
                bf[ni][1] = frag<CVTB>(Bs_[n0 * 20 + kb + 4]);
            }
            #pragma unroll
            for (int mi = 0; mi < 4; mi++)
                #pragma unroll
                for (int ni = 0; ni < 4; ni++)
                    mma_tf32(acc[mi][ni], af[mi], bf[ni]);
        }
        __syncthreads();
        if (ch + 2 < nc) NT_ISSUE((ch + 2) % 3, (ch + 2) * 16);
    }
    #undef NT_ISSUE

    // staged epilogue: two 64x128 halves through smem
    float* stg = dsm;
    #pragma unroll
    for (int half = 0; half < 2; half++) {
        if (wm == half) {
            #pragma unroll
            for (int mi = 0; mi < 4; mi++) {
                const int rr = mi * 16 + lr;
                #pragma unroll
                for (int ni = 0; ni < 4; ni++) {
                    const int cc = wn * 32 + ni * 8 + q * 2;
                    float v0 = acc[mi][ni][0] * alpha, v1 = acc[mi][ni][1] * alpha;
                    float v2 = acc[mi][ni][2] * alpha, v3 = acc[mi][ni][3] * alpha;
                    if (CVTO) {
                        v0 = __uint_as_float(f2tf32(v0));
                        v1 = __uint_as_float(f2tf32(v1));
                        v2 = __uint_as_float(f2tf32(v2));
                        v3 = __uint_as_float(f2tf32(v3));
                    }
                    stg[rr * 132 + cc]           = v0;
                    stg[rr * 132 + cc + 1]       = v1;
                    stg[(rr + 8) * 132 + cc]     = v2;
                    stg[(rr + 8) * 132 + cc + 1] = v3;
                }
            }
        }
        __syncthreads();
        #pragma unroll
        for (int i = 0; i < 8; i++) {
            const int row = (tid >> 5) * 8 + i;
            const int col = (tid & 31) * 4;
            *(float4*)&C[(size_t)(mBase + half * 64 + row) * ldc + nBase + col] =
                *(const float4*)&stg[row * 132 + col];
        }
        __syncthreads();
    }
}

// ---------------------------------------------------------------------------
__global__ __launch_bounds__(256, 2) void qkv_proj_kernel(
    const float* __restrict__ q, const float* __restrict__ k, const float* __restrict__ v,
    const float* __restrict__ Wq, const float* __restrict__ Wk, const float* __restrict__ Wv,
    float* __restrict__ qp, float* __restrict__ kp, float* __restrict__ vp)
{
    extern __shared__ float dsm[];
    const float* A; const float* B; float* C;
    if (blockIdx.z == 0)      { A = q; B = Wq; C = qp; }
    else if (blockIdx.z == 1) { A = k; B = Wk; C = kp; }
    else                      { A = v; B = Wv; C = vp; }
    gemm_nt_core<true, true, true>(A, B, C, DMODEL, DMODEL, DMODEL, DMODEL, 1.f,
                                   blockIdx.y * 128, blockIdx.x * 128, dsm);
}

__global__ __launch_bounds__(256, 2) void out_proj_kernel(
    const float* __restrict__ A, const float* __restrict__ B, float* __restrict__ C)
{
    extern __shared__ float dsm[];
    gemm_nt_core<false, true, false>(A, B, C, DMODEL, DMODEL, DMODEL, DMODEL, 1.f,
                                     blockIdx.y * 128, blockIdx.x * 128, dsm);
}

__global__ __launch_bounds__(256, 2) void scores_kernel(
    const float* __restrict__ qp, const float* __restrict__ kp, float* __restrict__ wts)
{
    extern __shared__ float dsm[];
    const int bh = blockIdx.z;
    const int b = bh >> 4, h = bh & 15;
    const float* A = qp + (size_t)b * SEQ * DMODEL + h * DK;
    const float* B = kp + (size_t)b * SEQ * DMODEL + h * DK;
    float*       C = wts + (size_t)bh * SEQ * SEQ;
    gemm_nt_core<false, false, false>(A, B, C, DK, DMODEL, DMODEL, SEQ, 0.125f,
                                      blockIdx.y * 128, blockIdx.x * 128, dsm);
}

// ---------------------------------------------------------------------------
// Row softmax, in place, float4 path: 65536 rows of 2048.
// ---------------------------------------------------------------------------
__global__ __launch_bounds__(256) void softmax_kernel(float* __restrict__ Wt)
{
    float4* row4 = (float4*)(Wt + (size_t)blockIdx.x * SEQ);
    const int tid = threadIdx.x;
    __shared__ float red[8];

    float4 a = row4[tid];
    float4 b = row4[tid + 256];

    float m = fmaxf(fmaxf(fmaxf(a.x, a.y), fmaxf(a.z, a.w)),
                    fmaxf(fmaxf(b.x, b.y), fmaxf(b.z, b.w)));
    #pragma unroll
    for (int o = 16; o; o >>= 1) m = fmaxf(m, __shfl_xor_sync(0xFFFFFFFFu, m, o));
    if ((tid & 31) == 0) red[tid >> 5] = m;
    __syncthreads();
    m = red[0];
    #pragma unroll
    for (int i = 1; i < 8; i++) m = fmaxf(m, red[i]);
    __syncthreads();

    a.x = __expf(a.x - m); a.y = __expf(a.y - m);
    a.z = __expf(a.z - m); a.w = __expf(a.w - m);
    b.x = __expf(b.x - m); b.y = __expf(b.y - m);
    b.z = __expf(b.z - m); b.w = __expf(b.w - m);

    float s = a.x + a.y + a.z + a.w + b.x + b.y + b.z + b.w;
    #pragma unroll
    for (int o = 16; o; o >>= 1) s += __shfl_xor_sync(0xFFFFFFFFu, s, o);
    if ((tid & 31) == 0) red[tid >> 5] = s;
    __syncthreads();
    s = red[0];
    #pragma unroll
    for (int i = 1; i < 8; i++) s += red[i];
    const float inv = 1.f / s;

    a.x *= inv; a.y *= inv; a.z *= inv; a.w *= inv;
    b.x *= inv; b.y *= inv; b.z *= inv; b.w *= inv;
    row4[tid]       = a;
    row4[tid + 256] = b;
}

// ---------------------------------------------------------------------------
// PV: C[128,64] tiles = P @ V. 4-stage cp.async, 3 CTAs/SM.
// P cvt'd in-loop (fp32 softmax values); V pre-rounded. ao stored tf32-rounded.
// Stage = As 128x20 (2560) + Bs 16x72 (1152) = 3712 floats (14848 B).
// ---------------------------------------------------------------------------
__global__ __launch_bounds__(256, 3) void pv_async_kernel(
    const float* __restrict__ P, const float* __restrict__ V, float* __restrict__ C)
{
    extern __shared__ float sm[];

    const int z = blockIdx.z;
    const int b = z >> 4, h = z & 15;
    const int mBase = blockIdx.y * 128;

    const float* Ag = P + (size_t)z * SEQ * SEQ + (size_t)mBase * SEQ;
    const float* Bg = V + (size_t)b * SEQ * DMODEL + h * DK;
    float*       Cg = C + (size_t)b * SEQ * DMODEL + h * DK + (size_t)mBase * DMODEL;

    const int tid  = threadIdx.x;
    const int lane = tid & 31;
    const int warp = tid >> 5;
    const int wm   = warp >> 1;
    const int wn   = warp & 1;
    const int q    = lane & 3;
    const int lr   = lane >> 2;
    const int r0   = tid >> 2;
    const int c4   = (tid & 3) << 2;
    const int kr   = tid >> 4;
    const int n4   = (tid & 15) << 2;

    const uint32_t sbase = (uint32_t)__cvta_generic_to_shared(sm);

    float acc[2][4][4];
    #pragma unroll
    for (int i = 0; i < 2; i++)
        #pragma unroll
        for (int j = 0; j < 4; j++)
            #pragma unroll
            for (int t = 0; t < 4; t++) acc[i][j][t] = 0.f;

    #define PV_ISSUE(st, k0) do {                                               \
        uint32_t ab = sbase + (st) * 14848u + (uint32_t)(r0 * 80 + c4 * 4);     \
        uint32_t bb = sbase + (st) * 14848u + 10240u + (uint32_t)(kr * 288 + n4 * 4); \
        cp16(ab,         Ag + (size_t)r0 * SEQ + (k0) + c4);                    \
        cp16(ab + 5120u, Ag + (size_t)(r0 + 64) * SEQ + (k0) + c4);             \
        cp16(bb,         Bg + (size_t)((k0) + kr) * DMODEL + n4);               \
        cp_commit();                                                            \
    } while (0)

    const int nc = SEQ >> 4;   // 128
    PV_ISSUE(0, 0);
    PV_ISSUE(1, 16);
    PV_ISSUE(2, 32);

    for (int ch = 0; ch < nc; ch++) {
        const int rem = nc - 1 - ch;           // groups issued beyond ch
        if (rem >= 2) cp_wait2();
        else if (rem == 1) cp_wait1();
        else cp_wait0();
        __syncthreads();

        const float* As_ = sm + (ch & 3) * 3712;
        const float* Bs_ = As_ + 2560;

        #pragma unroll
        for (int ks = 0; ks < 2; ks++) {
            const int kb = ks * 8 + q;
            uint32_t af[2][4], bf[4][2];
            #pragma unroll
            for (int mi = 0; mi < 2; mi++) {
                const int m0 = wm * 32 + mi * 16 + lr;
                af[mi][0] = f2tf32(As_[m0 * 20 + kb]);
                af[mi][1] = f2tf32(As_[(m0 + 8) * 20 + kb]);
                af[mi][2] = f2tf32(As_[m0 * 20 + kb + 4]);
                af[mi][3] = f2tf32(As_[(m0 + 8) * 20 + kb + 4]);
            }
            #pragma unroll
            for (int ni = 0; ni < 4; ni++) {
                const int n0 = wn * 32 + ni * 8 + lr;
                bf[ni][0] = __float_as_uint(Bs_[kb * 72 + n0]);
                bf[ni][1] = __float_as_uint(Bs_[(kb + 4) * 72 + n0]);
            }
            #pragma unroll
            for (int mi = 0; mi < 2; mi++)
                #pragma unroll
                for (int ni = 0; ni < 4; ni++)
                    mma_tf32(acc[mi][ni], af[mi], bf[ni]);
        }
        __syncthreads();
        if (ch + 3 < nc) PV_ISSUE((ch + 3) & 3, (ch + 3) * 16);
    }
    #undef PV_ISSUE

    // staged epilogue (output tf32-rounded; consumed only by out-proj MMA)
    float* stg = sm;
    #pragma unroll
    for (int mi = 0; mi < 2; mi++) {
        const int rr = wm * 32 + mi * 16 + lr;
        #pragma unroll
        for (int ni = 0; ni < 4; ni++) {
            const int cc = wn * 32 + ni * 8 + q * 2;
            stg[rr * 68 + cc]           = __uint_as_float(f2tf32(acc[mi][ni][0]));
            stg[rr * 68 + cc + 1]       = __uint_as_float(f2tf32(acc[mi][ni][1]));
            stg[(rr + 8) * 68 + cc]     = __uint_as_float(f2tf32(acc[mi][ni][2]));
            stg[(rr + 8) * 68 + cc + 1] = __uint_as_float(f2tf32(acc[mi][ni][3]));
        }
    }
    __syncthreads();
    #pragma unroll
    for (int i = 0; i < 8; i++) {
        const int row = (tid >> 4) * 8 + i;
        const int col = (tid & 15) * 4;
        *(float4*)&Cg[(size_t)row * DMODEL + col] = *(const float4*)&stg[row * 68 + col];
    }
}

// ---------------------------------------------------------------------------
extern "C" void kernel_launch(void* const* d_in, const int* in_sizes, int n_in,
                              void* d_out, int out_size)
{
    const float* q  = (const float*)d_in[0];
    const float* k  = (const float*)d_in[1];
    const float* v  = (const float*)d_in[2];
    const float* Wq = (const float*)d_in[3];
    const float* Wk = (const float*)d_in[4];
    const float* Wv = (const float*)d_in[5];
    const float* Wo = (const float*)d_in[6];
    float* out = (float*)d_out;
    float* wts = out + OUT_OFF;

    float *qp, *kp, *vp, *ao;
    cudaGetSymbolAddress((void**)&qp, g_qp);
    cudaGetSymbolAddress((void**)&kp, g_kp);
    cudaGetSymbolAddress((void**)&vp, g_vp);
    cudaGetSymbolAddress((void**)&ao, g_ao);

    const int DSM    = 3 * 20480;   // 61440 B (NT kernels)
    const int PV_DSM = 4 * 14848;   // 59392 B (PV, 4 stages)
    cudaFuncSetAttribute(qkv_proj_kernel, cudaFuncAttributeMaxDynamicSharedMemorySize, DSM);
    cudaFuncSetAttribute(scores_kernel,  cudaFuncAttributeMaxDynamicSharedMemorySize, DSM);
    cudaFuncSetAttribute(out_proj_kernel, cudaFuncAttributeMaxDynamicSharedMemorySize, DSM);
    cudaFuncSetAttribute(pv_async_kernel, cudaFuncAttributeMaxDynamicSharedMemorySize, PV_DSM);

    const dim3 thr(256);

    // Q/K/V projections in one launch (outputs tf32-rounded)
    qkv_proj_kernel<<<dim3(8, 32, 3), thr, DSM>>>(q, k, v, Wq, Wk, Wv, qp, kp, vp);

    // Scores: per (b,h) Qh @ Kh^T * 0.125 (no in-loop cvt)
    scores_kernel<<<dim3(16, 16, 32), thr, DSM>>>(qp, kp, wts);

    // Softmax in place
    softmax_kernel<<<BATCH * NHEAD * SEQ, 256>>>(wts);

    // P @ V -> attn_out (stored tf32-rounded)
    pv_async_kernel<<<dim3(1, 16, 32), thr, PV_DSM>>>(wts, vp, ao);

    // Output projection
    out_proj_kernel<<<dim3(8, 32, 1), thr, DSM>>>(ao, Wo, out);
}